// round 1
// baseline (speedup 1.0000x reference)
#include <cuda_runtime.h>
#include <math.h>

#define Bc 16
#define Sc 512
#define Dc 1024
#define Hc 8
#define DFFc 4096
#define DKc 128
#define MROWS (Bc*Sc)
#define NEGF (-1e32f)

// ---------------- scratch (device globals; no allocation allowed) ----------------
__device__ float g_y[(size_t)MROWS*Dc];
__device__ float g_xb[(size_t)MROWS*Dc];
__device__ float g_cat[(size_t)MROWS*Dc];
__device__ float g_proj[(size_t)MROWS*Dc];
__device__ float g_qk[(size_t)MROWS*Dc];
__device__ float g_v[(size_t)MROWS*Dc];
__device__ float g_att[(size_t)MROWS*Dc];
__device__ float g_scores[(size_t)Bc*Hc*Sc*Sc];
__device__ float g_ff[(size_t)MROWS*DFFc];
__device__ int   g_ext[Hc*Sc];

// ---------------- GEMM: C = alpha * A(M,K) @ B(N,K)^T + bias, NT layout ----------
// 128x128 tile, BK=16, 256 threads, 8x8 micro-tile.
__global__ __launch_bounds__(256, 2)
void gemm_nt(const float* __restrict__ A, const float* __restrict__ Bm,
             const float* __restrict__ bias, float* __restrict__ C,
             int M, int N, int K,
             long sA, long sB, long sC, float alpha, int relu)
{
    __shared__ float As[16][128];
    __shared__ float Bs[16][128];
    const int tid = threadIdx.x;
    const float* Ab = A + (long)blockIdx.z * sA + (long)blockIdx.y * 128 * K;
    const float* Bb = Bm + (long)blockIdx.z * sB + (long)blockIdx.x * 128 * K;
    float acc[8][8];
#pragma unroll
    for (int i = 0; i < 8; i++)
#pragma unroll
        for (int j = 0; j < 8; j++) acc[i][j] = 0.f;

    const int ty = tid >> 4, tx = tid & 15;
    const int lr = tid >> 2;          // 0..63
    const int lc = (tid & 3) << 2;    // 0,4,8,12

    for (int k0 = 0; k0 < K; k0 += 16) {
#pragma unroll
        for (int p = 0; p < 2; p++) {
            int r = lr + p * 64;
            float4 a = *(const float4*)(Ab + (long)r * K + k0 + lc);
            As[lc+0][r] = a.x; As[lc+1][r] = a.y; As[lc+2][r] = a.z; As[lc+3][r] = a.w;
            float4 b = *(const float4*)(Bb + (long)r * K + k0 + lc);
            Bs[lc+0][r] = b.x; Bs[lc+1][r] = b.y; Bs[lc+2][r] = b.z; Bs[lc+3][r] = b.w;
        }
        __syncthreads();
#pragma unroll
        for (int kk = 0; kk < 16; kk++) {
            float af[8], bf[8];
            *(float4*)&af[0] = *(const float4*)&As[kk][ty*8];
            *(float4*)&af[4] = *(const float4*)&As[kk][ty*8+4];
            *(float4*)&bf[0] = *(const float4*)&Bs[kk][tx*8];
            *(float4*)&bf[4] = *(const float4*)&Bs[kk][tx*8+4];
#pragma unroll
            for (int i = 0; i < 8; i++)
#pragma unroll
                for (int j = 0; j < 8; j++)
                    acc[i][j] = fmaf(af[i], bf[j], acc[i][j]);
        }
        __syncthreads();
    }

    float* Cb = C + (long)blockIdx.z * sC;
    const int rbase = blockIdx.y * 128 + ty * 8;
    const int cbase = blockIdx.x * 128 + tx * 8;
#pragma unroll
    for (int i = 0; i < 8; i++) {
        float4 v0, v1;
        float bv[8];
#pragma unroll
        for (int j = 0; j < 8; j++) {
            float v = acc[i][j] * alpha;
            if (bias) v += bias[cbase + j];
            if (relu) v = fmaxf(v, 0.f);
            bv[j] = v;
        }
        v0 = make_float4(bv[0], bv[1], bv[2], bv[3]);
        v1 = make_float4(bv[4], bv[5], bv[6], bv[7]);
        *(float4*)(Cb + (long)(rbase + i) * N + cbase)     = v0;
        *(float4*)(Cb + (long)(rbase + i) * N + cbase + 4) = v1;
    }
}

// ---------------- GEMM NN: C = A(M,K) @ B(K,N) (B row-major K x N) --------------
// Used for att @ V (per-batch 512x512 @ 512x128). N must be multiple of 4, tile 128.
__global__ __launch_bounds__(256, 2)
void gemm_nn(const float* __restrict__ A, const float* __restrict__ Bm,
             float* __restrict__ C,
             int M, int N, int K,
             long sA, long sB, long sC)
{
    __shared__ float As[16][128];
    __shared__ float Bs[16][128];
    const int tid = threadIdx.x;
    const float* Ab = A + (long)blockIdx.z * sA + (long)blockIdx.y * 128 * K;
    const float* Bb = Bm + (long)blockIdx.z * sB + (long)blockIdx.x * 128;
    float acc[8][8];
#pragma unroll
    for (int i = 0; i < 8; i++)
#pragma unroll
        for (int j = 0; j < 8; j++) acc[i][j] = 0.f;

    const int ty = tid >> 4, tx = tid & 15;
    const int lr = tid >> 2;
    const int lc = (tid & 3) << 2;
    const int bkr = tid >> 5;          // 0..7
    const int bnc = (tid & 31) << 2;   // 0..124

    for (int k0 = 0; k0 < K; k0 += 16) {
#pragma unroll
        for (int p = 0; p < 2; p++) {
            int r = lr + p * 64;
            float4 a = *(const float4*)(Ab + (long)r * K + k0 + lc);
            As[lc+0][r] = a.x; As[lc+1][r] = a.y; As[lc+2][r] = a.z; As[lc+3][r] = a.w;
            int kr = bkr + p * 8;
            float4 b = *(const float4*)(Bb + (long)(k0 + kr) * N + bnc);
            *(float4*)&Bs[kr][bnc] = b;
        }
        __syncthreads();
#pragma unroll
        for (int kk = 0; kk < 16; kk++) {
            float af[8], bf[8];
            *(float4*)&af[0] = *(const float4*)&As[kk][ty*8];
            *(float4*)&af[4] = *(const float4*)&As[kk][ty*8+4];
            *(float4*)&bf[0] = *(const float4*)&Bs[kk][tx*8];
            *(float4*)&bf[4] = *(const float4*)&Bs[kk][tx*8+4];
#pragma unroll
            for (int i = 0; i < 8; i++)
#pragma unroll
                for (int j = 0; j < 8; j++)
                    acc[i][j] = fmaf(af[i], bf[j], acc[i][j]);
        }
        __syncthreads();
    }

    float* Cb = C + (long)blockIdx.z * sC;
    const int rbase = blockIdx.y * 128 + ty * 8;
    const int cbase = blockIdx.x * 128 + tx * 8;
#pragma unroll
    for (int i = 0; i < 8; i++) {
        *(float4*)(Cb + (long)(rbase + i) * N + cbase)     = make_float4(acc[i][0], acc[i][1], acc[i][2], acc[i][3]);
        *(float4*)(Cb + (long)(rbase + i) * N + cbase + 4) = make_float4(acc[i][4], acc[i][5], acc[i][6], acc[i][7]);
    }
}

// ---------------- layout reshapes ------------------------------------------------
// (B,S,D) -> (B,H,S,DK)
__global__ void to_heads(const float* __restrict__ in, float* __restrict__ out)
{
    int t = blockIdx.x * blockDim.x + threadIdx.x;   // over B*H*S*DK/4
    int dq = t & (DKc/4 - 1);
    int rest = t >> 5;               // /(DK/4)=32
    int s = rest & (Sc - 1); rest >>= 9;
    int h = rest & (Hc - 1);
    int b = rest >> 3;
    float4 v = *(const float4*)(in + ((long)(b*Sc + s) * Dc + h*DKc + dq*4));
    *(float4*)(out + (long)t * 4) = v;
}

// (B,H,S,DK) -> (B,S,D)
__global__ void from_heads(const float* __restrict__ in, float* __restrict__ out)
{
    int t = blockIdx.x * blockDim.x + threadIdx.x;   // over B*S*D/4
    int cq = t & (Dc/4 - 1);
    int rest = t >> 8;               // /(D/4)=256
    int s = rest & (Sc - 1);
    int b = rest >> 9;
    int c = cq * 4;
    int h = c / DKc;
    int d = c - h * DKc;
    float4 v = *(const float4*)(in + ((long)((b*Hc + h)*Sc + s) * DKc + d));
    *(float4*)(out + (long)t * 4) = v;
}

// ---------------- dam "ext" bits ------------------------------------------------
__global__ void compute_ext(const float* __restrict__ alphas, const float* __restrict__ E,
                            int* __restrict__ ext)
{
    int idx = blockIdx.x * blockDim.x + threadIdx.x;  // H*S
    if (idx < Hc * Sc) {
        float a0 = alphas[idx*2], a1 = alphas[idx*2+1];
        float g0 = -logf(E[idx*2] + 1e-5f), g1 = -logf(E[idx*2+1] + 1e-5f);
        ext[idx] = ((a0 + g0) < (a1 + g1)) ? 1 : 0;
    }
}

// ---------------- fused dam-softmax / cumdist / decay / softmax ------------------
// One 512-thread block per (b,h,i) row, in place on scores.
__global__ __launch_bounds__(512)
void attn_softmax(float* __restrict__ scores, const int* __restrict__ ext,
                  const float* __restrict__ gam, int bmask, int zero_pad)
{
    const int i = blockIdx.x, h = blockIdx.y, b = blockIdx.z;
    const int j = threadIdx.x;
    __shared__ float red[512];

    float* row = scores + ((((long)b * Hc + h) * Sc + i) * Sc);
    float raw = row[j];
    int delta = j - i; if (delta < 0) delta = -delta;
    bool causal = (j < i + bmask);
    bool dam = causal || (ext[h * Sc + delta] != 0);

    // --- softmax 1 over dam mask ---
    float v1 = dam ? raw : NEGF;
    red[j] = v1; __syncthreads();
    for (int off = 256; off; off >>= 1) {
        if (j < off) red[j] = fmaxf(red[j], red[j + off]);
        __syncthreads();
    }
    float mx = red[0]; __syncthreads();
    float e1 = expf(v1 - mx);
    red[j] = e1; __syncthreads();
    for (int off = 256; off; off >>= 1) {
        if (j < off) red[j] += red[j + off];
        __syncthreads();
    }
    float s1 = red[0]; __syncthreads();
    float p = e1 / s1;

    // --- restrict to causal, inclusive cumsum ---
    float sc = causal ? p : 0.f;
    red[j] = sc; __syncthreads();
    for (int off = 1; off < 512; off <<= 1) {
        float t = (j >= off) ? red[j - off] : 0.f;
        __syncthreads();
        red[j] += t;
        __syncthreads();
    }
    float cum = red[j];
    float tot = red[511];
    __syncthreads();

    // --- distance decay ---
    float rem = tot - cum;
    float dist = sqrtf(fmaxf(rem * (float)delta, 0.f));
    float g = gam[h];
    float sp = (g > 20.f) ? g : log1pf(expf(g));
    float te = expf(dist * (-sp));
    te = fminf(fmaxf(te, 1e-5f), 1e5f);

    // --- softmax 2 over causal region with rescored logits ---
    float v2 = causal ? raw * te : NEGF;
    red[j] = v2; __syncthreads();
    for (int off = 256; off; off >>= 1) {
        if (j < off) red[j] = fmaxf(red[j], red[j + off]);
        __syncthreads();
    }
    float mx2 = red[0]; __syncthreads();
    float e2 = expf(v2 - mx2);
    red[j] = e2; __syncthreads();
    for (int off = 256; off; off >>= 1) {
        if (j < off) red[j] += red[j + off];
        __syncthreads();
    }
    float s2 = red[0];
    float out = e2 / s2;
    if (zero_pad && i == 0) out = 0.f;
    row[j] = out;
}

// ---------------- residual + layernorm ------------------------------------------
__global__ __launch_bounds__(256)
void add_ln(const float* __restrict__ a, const float* __restrict__ c,
            const float* __restrict__ g, const float* __restrict__ bt,
            float* __restrict__ out)
{
    const int r = blockIdx.x;
    const long base = (long)r * Dc;
    __shared__ float red[256];
    float vals[4];
    float s = 0.f;
#pragma unroll
    for (int q = 0; q < 4; q++) {
        int cidx = threadIdx.x + q * 256;
        vals[q] = a[base + cidx] + c[base + cidx];
        s += vals[q];
    }
    red[threadIdx.x] = s; __syncthreads();
    for (int off = 128; off; off >>= 1) {
        if (threadIdx.x < off) red[threadIdx.x] += red[threadIdx.x + off];
        __syncthreads();
    }
    float mu = red[0] * (1.f / Dc); __syncthreads();
    float vs = 0.f;
#pragma unroll
    for (int q = 0; q < 4; q++) { float d = vals[q] - mu; vs += d * d; }
    red[threadIdx.x] = vs; __syncthreads();
    for (int off = 128; off; off >>= 1) {
        if (threadIdx.x < off) red[threadIdx.x] += red[threadIdx.x + off];
        __syncthreads();
    }
    float var = red[0] * (1.f / Dc);
    float inv = rsqrtf(var + 1e-5f);
#pragma unroll
    for (int q = 0; q < 4; q++) {
        int cidx = threadIdx.x + q * 256;
        out[base + cidx] = (vals[q] - mu) * inv * g[cidx] + bt[cidx];
    }
}

// ---------------- host orchestration --------------------------------------------
struct Scratch {
    float *y, *xb, *cat, *proj, *qk, *v, *att, *scores, *ff;
    int* ext;
};

static void run_layer(const float* X, const float* Vin, float* outbuf,
                      int l, int bmask, int apply_pos,
                      const float* kW, const float* kb,
                      const float* vW, const float* vb,
                      const float* oW, const float* ob,
                      const float* gammas, const float* alphas, const float* gE,
                      const float* ln1g, const float* ln1b,
                      const float* w1, const float* b1,
                      const float* w2, const float* b2,
                      const float* ln2g, const float* ln2b,
                      const Scratch& S)
{
    const long DD = (long)Dc * Dc;
    const float one = 1.0f;
    const float scl = 1.0f / sqrtf((float)DKc);

    // q(=k) projection
    gemm_nt<<<dim3(Dc/128, MROWS/128), 256>>>(X, kW + (long)l*DD, kb + (long)l*Dc, S.cat,
                                              MROWS, Dc, Dc, 0, 0, 0, one, 0);
    to_heads<<<(MROWS*Dc/4)/256, 256>>>(S.cat, S.qk);
    // v projection
    gemm_nt<<<dim3(Dc/128, MROWS/128), 256>>>(Vin, vW + (long)l*DD, vb + (long)l*Dc, S.cat,
                                              MROWS, Dc, Dc, 0, 0, 0, one, 0);
    to_heads<<<(MROWS*Dc/4)/256, 256>>>(S.cat, S.v);

    // scores = q @ q^T / sqrt(dk), batched over B*H
    gemm_nt<<<dim3(Sc/128, Sc/128, Bc*Hc), 256>>>(S.qk, S.qk, nullptr, S.scores,
                                                  Sc, Sc, DKc,
                                                  (long)Sc*DKc, (long)Sc*DKc, (long)Sc*Sc,
                                                  scl, 0);

    compute_ext<<<(Hc*Sc + 255)/256, 256>>>(alphas + (long)l*Hc*Sc*2, gE + (long)l*Hc*Sc*2, S.ext);
    attn_softmax<<<dim3(Sc, Hc, Bc), 512>>>(S.scores, S.ext, gammas + (long)l*Hc, bmask, bmask == 0);

    // att = scores @ v, batched
    gemm_nn<<<dim3(DKc/128, Sc/128, Bc*Hc), 256>>>(S.scores, S.v, S.att,
                                                   Sc, DKc, Sc,
                                                   (long)Sc*Sc, (long)Sc*DKc, (long)Sc*DKc);
    from_heads<<<(MROWS*Dc/4)/256, 256>>>(S.att, S.cat);

    // output projection + residual LN
    gemm_nt<<<dim3(Dc/128, MROWS/128), 256>>>(S.cat, oW + (long)l*DD, ob + (long)l*Dc, S.proj,
                                              MROWS, Dc, Dc, 0, 0, 0, one, 0);
    add_ln<<<MROWS, 256>>>(X, S.proj, ln1g + (long)l*Dc, ln1b + (long)l*Dc, outbuf);

    if (apply_pos) {
        gemm_nt<<<dim3(DFFc/128, MROWS/128), 256>>>(outbuf, w1 + (long)l*DFFc*Dc, b1 + (long)l*DFFc, S.ff,
                                                    MROWS, DFFc, Dc, 0, 0, 0, one, 1);
        gemm_nt<<<dim3(Dc/128, MROWS/128), 256>>>(S.ff, w2 + (long)l*Dc*DFFc, b2 + (long)l*Dc, S.proj,
                                                  MROWS, Dc, DFFc, 0, 0, 0, one, 0);
        add_ln<<<MROWS, 256>>>(outbuf, S.proj, ln2g + (long)l*Dc, ln2b + (long)l*Dc, outbuf);
    }
}

extern "C" void kernel_launch(void* const* d_in, const int* in_sizes, int n_in,
                              void* d_out, int out_size)
{
    const float* q_embed  = (const float*)d_in[0];
    const float* qa_embed = (const float*)d_in[1];
    const float* kW = (const float*)d_in[2];
    const float* kb = (const float*)d_in[3];
    const float* vW = (const float*)d_in[4];
    const float* vb = (const float*)d_in[5];
    const float* oW = (const float*)d_in[6];
    const float* ob = (const float*)d_in[7];
    const float* gammas = (const float*)d_in[8];
    const float* alphas = (const float*)d_in[9];
    const float* ln1g = (const float*)d_in[10];
    const float* ln1b = (const float*)d_in[11];
    const float* w1 = (const float*)d_in[12];
    const float* b1 = (const float*)d_in[13];
    const float* w2 = (const float*)d_in[14];
    const float* b2 = (const float*)d_in[15];
    const float* ln2g = (const float*)d_in[16];
    const float* ln2b = (const float*)d_in[17];
    const float* gE = (const float*)d_in[18];
    float* out = (float*)d_out;

    Scratch S;
    cudaGetSymbolAddress((void**)&S.y, g_y);
    cudaGetSymbolAddress((void**)&S.xb, g_xb);
    cudaGetSymbolAddress((void**)&S.cat, g_cat);
    cudaGetSymbolAddress((void**)&S.proj, g_proj);
    cudaGetSymbolAddress((void**)&S.qk, g_qk);
    cudaGetSymbolAddress((void**)&S.v, g_v);
    cudaGetSymbolAddress((void**)&S.att, g_att);
    cudaGetSymbolAddress((void**)&S.scores, g_scores);
    cudaGetSymbolAddress((void**)&S.ff, g_ff);
    cudaGetSymbolAddress((void**)&S.ext, g_ext);

    // y = layer0(qa, qa, qa), bmask=1, with FFN
    run_layer(qa_embed, qa_embed, S.y, 0, 1, 1,
              kW, kb, vW, vb, oW, ob, gammas, alphas, gE,
              ln1g, ln1b, w1, b1, w2, b2, ln2g, ln2b, S);
    // x = layer1(q, q, q), bmask=1, no FFN
    run_layer(q_embed, q_embed, S.xb, 1, 1, 0,
              kW, kb, vW, vb, oW, ob, gammas, alphas, gE,
              ln1g, ln1b, w1, b1, w2, b2, ln2g, ln2b, S);
    // out = layer2(x, x, y), bmask=0, with FFN
    run_layer(S.xb, S.y, out, 2, 0, 1,
              kW, kb, vW, vb, oW, ob, gammas, alphas, gE,
              ln1g, ln1b, w1, b1, w2, b2, ln2g, ln2b, S);
}

// round 2
// speedup vs baseline: 2.6386x; 2.6386x over previous
#include <cuda_runtime.h>
#include <math.h>
#include <stdint.h>

#define Bc 16
#define Sc 512
#define Dc 1024
#define Hc 8
#define DFFc 4096
#define DKc 128
#define MROWS (Bc*Sc)
#define NEGF (-1e32f)

// ---------------- scratch (device globals; no allocation allowed) ----------------
__device__ float g_y[(size_t)MROWS*Dc];
__device__ float g_xb[(size_t)MROWS*Dc];
__device__ float g_cat[(size_t)MROWS*Dc];
__device__ float g_proj[(size_t)MROWS*Dc];
__device__ float g_qk[(size_t)MROWS*Dc];
__device__ float g_v[(size_t)MROWS*Dc];     // head-transposed: [B,H,DK,S]
__device__ float g_att[(size_t)MROWS*Dc];
__device__ float g_scores[(size_t)Bc*Hc*Sc*Sc];
__device__ float g_ff[(size_t)MROWS*DFFc];
__device__ int   g_ext[Hc*Sc];

__device__ __forceinline__ uint32_t cvt_tf32(float x) {
    uint32_t r;
    asm("cvt.rna.tf32.f32 %0, %1;" : "=r"(r) : "f"(x));
    return r;
}

// ---------------- TF32 tensor-core GEMM: C = alpha*A(M,K)@B(N,K)^T + bias -------
// Block tile 128x128, BK=16, 4 warps (64x64 each), mma.m16n8k8, double-buffered.
__global__ __launch_bounds__(128, 2)
void gemm_tf32(const float* __restrict__ A, const float* __restrict__ Bm,
               const float* __restrict__ bias, float* __restrict__ C,
               int M, int N, int K,
               long sA, long sB, long sC, float alpha, int relu)
{
    __shared__ float As[2][128*16];
    __shared__ float Bs[2][128*16];

    const int tid = threadIdx.x;
    const int warp = tid >> 5, lane = tid & 31;
    const int wm = warp >> 1, wn = warp & 1;      // 2x2 warp grid
    const int gid = lane >> 2, tig = lane & 3;

    const float* Ab = A + (long)blockIdx.z * sA + (long)blockIdx.y * 128 * K;
    const float* Bb = Bm + (long)blockIdx.z * sB + (long)blockIdx.x * 128 * K;

    float acc[4][8][4];
#pragma unroll
    for (int t = 0; t < 4; t++)
#pragma unroll
        for (int u = 0; u < 8; u++)
#pragma unroll
            for (int r = 0; r < 4; r++) acc[t][u][r] = 0.f;

    // loader mapping: 512 float4 per 128x16 tile, 4 per thread
    int lm[4], soff[4];
    long goff[4];
#pragma unroll
    for (int q = 0; q < 4; q++) {
        int idx = q * 128 + tid;
        int m = idx >> 2, c = idx & 3;
        lm[q] = m;
        goff[q] = (long)m * K + c * 4;
        soff[q] = m * 16 + (c ^ ((m >> 1) & 3)) * 4;
    }

    // ldmatrix per-thread row/chunk components
    const int lr8 = lane & 7;
    const int selA_row = ((lane >> 3) & 1) * 8;   // a: sel&1 -> +8 rows
    const int selA_k   = ((lane >> 4) & 1) * 4;   // a: sel>>1 -> +4 k
    const int selB_row = ((lane >> 4) & 1) * 8;   // b: sel>>1 -> +8 rows
    const int selB_k   = ((lane >> 3) & 1) * 4;   // b: sel&1 -> +4 k

    float4 ra[4], rb[4];
    // prologue: load k0=0
#pragma unroll
    for (int q = 0; q < 4; q++) {
        ra[q] = *(const float4*)(Ab + goff[q]);
        rb[q] = *(const float4*)(Bb + goff[q]);
    }
#pragma unroll
    for (int q = 0; q < 4; q++) {
        uint32_t* pa = (uint32_t*)&As[0][soff[q]];
        pa[0] = cvt_tf32(ra[q].x); pa[1] = cvt_tf32(ra[q].y);
        pa[2] = cvt_tf32(ra[q].z); pa[3] = cvt_tf32(ra[q].w);
        uint32_t* pb = (uint32_t*)&Bs[0][soff[q]];
        pb[0] = cvt_tf32(rb[q].x); pb[1] = cvt_tf32(rb[q].y);
        pb[2] = cvt_tf32(rb[q].z); pb[3] = cvt_tf32(rb[q].w);
    }
    __syncthreads();

    int nbuf = 0;
    for (int k0 = 0; k0 < K; k0 += 16) {
        if (k0 + 16 < K) {
#pragma unroll
            for (int q = 0; q < 4; q++) {
                ra[q] = *(const float4*)(Ab + goff[q] + k0 + 16);
                rb[q] = *(const float4*)(Bb + goff[q] + k0 + 16);
            }
        }

        uint32_t abase = (uint32_t)__cvta_generic_to_shared(&As[nbuf][0]);
        uint32_t bbase = (uint32_t)__cvta_generic_to_shared(&Bs[nbuf][0]);

#pragma unroll
        for (int ks = 0; ks < 2; ks++) {
            uint32_t a_frag[4][4], b_frag[8][2];
#pragma unroll
            for (int t = 0; t < 4; t++) {
                int row = wm * 64 + t * 16 + lr8 + selA_row;
                int chunk = (ks * 8 + selA_k) >> 2;
                int sw = chunk ^ ((row >> 1) & 3);
                uint32_t addr = abase + (uint32_t)(row * 16 + sw * 4) * 4u;
                asm volatile(
                    "ldmatrix.sync.aligned.m8n8.x4.shared.b16 {%0,%1,%2,%3}, [%4];"
                    : "=r"(a_frag[t][0]), "=r"(a_frag[t][1]),
                      "=r"(a_frag[t][2]), "=r"(a_frag[t][3])
                    : "r"(addr));
            }
#pragma unroll
            for (int p = 0; p < 4; p++) {
                int row = wn * 64 + p * 16 + lr8 + selB_row;
                int chunk = (ks * 8 + selB_k) >> 2;
                int sw = chunk ^ ((row >> 1) & 3);
                uint32_t addr = bbase + (uint32_t)(row * 16 + sw * 4) * 4u;
                asm volatile(
                    "ldmatrix.sync.aligned.m8n8.x4.shared.b16 {%0,%1,%2,%3}, [%4];"
                    : "=r"(b_frag[2*p][0]), "=r"(b_frag[2*p][1]),
                      "=r"(b_frag[2*p+1][0]), "=r"(b_frag[2*p+1][1])
                    : "r"(addr));
            }
#pragma unroll
            for (int t = 0; t < 4; t++)
#pragma unroll
                for (int u = 0; u < 8; u++) {
                    asm volatile(
                        "mma.sync.aligned.m16n8k8.row.col.f32.tf32.tf32.f32 "
                        "{%0,%1,%2,%3}, {%4,%5,%6,%7}, {%8,%9}, {%0,%1,%2,%3};"
                        : "+f"(acc[t][u][0]), "+f"(acc[t][u][1]),
                          "+f"(acc[t][u][2]), "+f"(acc[t][u][3])
                        : "r"(a_frag[t][0]), "r"(a_frag[t][1]),
                          "r"(a_frag[t][2]), "r"(a_frag[t][3]),
                          "r"(b_frag[u][0]), "r"(b_frag[u][1]));
                }
        }

        if (k0 + 16 < K) {
            int ob = nbuf ^ 1;
#pragma unroll
            for (int q = 0; q < 4; q++) {
                uint32_t* pa = (uint32_t*)&As[ob][soff[q]];
                pa[0] = cvt_tf32(ra[q].x); pa[1] = cvt_tf32(ra[q].y);
                pa[2] = cvt_tf32(ra[q].z); pa[3] = cvt_tf32(ra[q].w);
                uint32_t* pb = (uint32_t*)&Bs[ob][soff[q]];
                pb[0] = cvt_tf32(rb[q].x); pb[1] = cvt_tf32(rb[q].y);
                pb[2] = cvt_tf32(rb[q].z); pb[3] = cvt_tf32(rb[q].w);
            }
        }
        __syncthreads();
        nbuf ^= 1;
    }

    float* Cb = C + (long)blockIdx.z * sC;
    const int rb0 = blockIdx.y * 128 + wm * 64;
    const int cb0 = blockIdx.x * 128 + wn * 64;
#pragma unroll
    for (int t = 0; t < 4; t++) {
        int r0 = rb0 + t * 16 + gid;
#pragma unroll
        for (int u = 0; u < 8; u++) {
            int col = cb0 + u * 8 + tig * 2;
            float b0 = 0.f, b1 = 0.f;
            if (bias) { b0 = bias[col]; b1 = bias[col + 1]; }
            float v0 = acc[t][u][0] * alpha + b0;
            float v1 = acc[t][u][1] * alpha + b1;
            float v2 = acc[t][u][2] * alpha + b0;
            float v3 = acc[t][u][3] * alpha + b1;
            if (relu) {
                v0 = fmaxf(v0, 0.f); v1 = fmaxf(v1, 0.f);
                v2 = fmaxf(v2, 0.f); v3 = fmaxf(v3, 0.f);
            }
            *(float2*)(Cb + (long)r0 * N + col)       = make_float2(v0, v1);
            *(float2*)(Cb + (long)(r0 + 8) * N + col) = make_float2(v2, v3);
        }
    }
}

// ---------------- layout reshapes ------------------------------------------------
// (B,S,D) -> (B,H,S,DK)
__global__ void to_heads(const float* __restrict__ in, float* __restrict__ out)
{
    int t = blockIdx.x * blockDim.x + threadIdx.x;
    int dq = t & (DKc/4 - 1);
    int rest = t >> 5;
    int s = rest & (Sc - 1); rest >>= 9;
    int h = rest & (Hc - 1);
    int b = rest >> 3;
    float4 v = *(const float4*)(in + ((long)(b*Sc + s) * Dc + h*DKc + dq*4));
    *(float4*)(out + (long)t * 4) = v;
}

// (B,S,D) -> (B,H,DK,S)  (head-transposed, for NT att@v)
__global__ void to_heads_t(const float* __restrict__ in, float* __restrict__ out)
{
    int t = blockIdx.x * blockDim.x + threadIdx.x;   // B*H*(DK/4)*S
    int s = t & (Sc - 1);
    int rest = t >> 9;
    int dq = rest & (DKc/4 - 1);
    rest >>= 5;
    int h = rest & (Hc - 1);
    int b = rest >> 3;
    float4 v = *(const float4*)(in + ((long)(b*Sc + s) * Dc + h*DKc + dq*4));
    long ob = ((long)((b*Hc + h)*DKc) + dq*4) * Sc + s;
    out[ob]        = v.x;
    out[ob + Sc]   = v.y;
    out[ob + 2*Sc] = v.z;
    out[ob + 3*Sc] = v.w;
}

// (B,H,S,DK) -> (B,S,D)
__global__ void from_heads(const float* __restrict__ in, float* __restrict__ out)
{
    int t = blockIdx.x * blockDim.x + threadIdx.x;
    int cq = t & (Dc/4 - 1);
    int rest = t >> 8;
    int s = rest & (Sc - 1);
    int b = rest >> 9;
    int c = cq * 4;
    int h = c / DKc;
    int d = c - h * DKc;
    float4 v = *(const float4*)(in + ((long)((b*Hc + h)*Sc + s) * DKc + d));
    *(float4*)(out + (long)t * 4) = v;
}

// ---------------- dam "ext" bits ------------------------------------------------
__global__ void compute_ext(const float* __restrict__ alphas, const float* __restrict__ E,
                            int* __restrict__ ext)
{
    int idx = blockIdx.x * blockDim.x + threadIdx.x;
    if (idx < Hc * Sc) {
        float a0 = alphas[idx*2], a1 = alphas[idx*2+1];
        float g0 = -logf(E[idx*2] + 1e-5f), g1 = -logf(E[idx*2+1] + 1e-5f);
        ext[idx] = ((a0 + g0) < (a1 + g1)) ? 1 : 0;
    }
}

// ---------------- fused dam-softmax / cumdist / decay / softmax ------------------
__global__ __launch_bounds__(512)
void attn_softmax(float* __restrict__ scores, const int* __restrict__ ext,
                  const float* __restrict__ gam, int bmask, int zero_pad)
{
    const int i = blockIdx.x, h = blockIdx.y, b = blockIdx.z;
    const int j = threadIdx.x;
    __shared__ float red[512];

    float* row = scores + ((((long)b * Hc + h) * Sc + i) * Sc);
    float raw = row[j];
    int delta = j - i; if (delta < 0) delta = -delta;
    bool causal = (j < i + bmask);
    bool dam = causal || (ext[h * Sc + delta] != 0);

    float v1 = dam ? raw : NEGF;
    red[j] = v1; __syncthreads();
    for (int off = 256; off; off >>= 1) {
        if (j < off) red[j] = fmaxf(red[j], red[j + off]);
        __syncthreads();
    }
    float mx = red[0]; __syncthreads();
    float e1 = expf(v1 - mx);
    red[j] = e1; __syncthreads();
    for (int off = 256; off; off >>= 1) {
        if (j < off) red[j] += red[j + off];
        __syncthreads();
    }
    float s1 = red[0]; __syncthreads();
    float p = e1 / s1;

    float sc = causal ? p : 0.f;
    red[j] = sc; __syncthreads();
    for (int off = 1; off < 512; off <<= 1) {
        float t = (j >= off) ? red[j - off] : 0.f;
        __syncthreads();
        red[j] += t;
        __syncthreads();
    }
    float cum = red[j];
    float tot = red[511];
    __syncthreads();

    float rem = tot - cum;
    float dist = sqrtf(fmaxf(rem * (float)delta, 0.f));
    float g = gam[h];
    float sp = (g > 20.f) ? g : log1pf(expf(g));
    float te = expf(dist * (-sp));
    te = fminf(fmaxf(te, 1e-5f), 1e5f);

    float v2 = causal ? raw * te : NEGF;
    red[j] = v2; __syncthreads();
    for (int off = 256; off; off >>= 1) {
        if (j < off) red[j] = fmaxf(red[j], red[j + off]);
        __syncthreads();
    }
    float mx2 = red[0]; __syncthreads();
    float e2 = expf(v2 - mx2);
    red[j] = e2; __syncthreads();
    for (int off = 256; off; off >>= 1) {
        if (j < off) red[j] += red[j + off];
        __syncthreads();
    }
    float s2 = red[0];
    float out = e2 / s2;
    if (zero_pad && i == 0) out = 0.f;
    row[j] = out;
}

// ---------------- residual + layernorm ------------------------------------------
__global__ __launch_bounds__(256)
void add_ln(const float* __restrict__ a, const float* __restrict__ c,
            const float* __restrict__ g, const float* __restrict__ bt,
            float* __restrict__ out)
{
    const int r = blockIdx.x;
    const long base = (long)r * Dc;
    __shared__ float red[256];
    float vals[4];
    float s = 0.f;
#pragma unroll
    for (int q = 0; q < 4; q++) {
        int cidx = threadIdx.x + q * 256;
        vals[q] = a[base + cidx] + c[base + cidx];
        s += vals[q];
    }
    red[threadIdx.x] = s; __syncthreads();
    for (int off = 128; off; off >>= 1) {
        if (threadIdx.x < off) red[threadIdx.x] += red[threadIdx.x + off];
        __syncthreads();
    }
    float mu = red[0] * (1.f / Dc); __syncthreads();
    float vs = 0.f;
#pragma unroll
    for (int q = 0; q < 4; q++) { float d = vals[q] - mu; vs += d * d; }
    red[threadIdx.x] = vs; __syncthreads();
    for (int off = 128; off; off >>= 1) {
        if (threadIdx.x < off) red[threadIdx.x] += red[threadIdx.x + off];
        __syncthreads();
    }
    float var = red[0] * (1.f / Dc);
    float inv = rsqrtf(var + 1e-5f);
#pragma unroll
    for (int q = 0; q < 4; q++) {
        int cidx = threadIdx.x + q * 256;
        out[base + cidx] = (vals[q] - mu) * inv * g[cidx] + bt[cidx];
    }
}

// ---------------- host orchestration --------------------------------------------
struct Scratch {
    float *y, *xb, *cat, *proj, *qk, *v, *att, *scores, *ff;
    int* ext;
};

static void run_layer(const float* X, const float* Vin, float* outbuf,
                      int l, int bmask, int apply_pos,
                      const float* kW, const float* kb,
                      const float* vW, const float* vb,
                      const float* oW, const float* ob,
                      const float* gammas, const float* alphas, const float* gE,
                      const float* ln1g, const float* ln1b,
                      const float* w1, const float* b1,
                      const float* w2, const float* b2,
                      const float* ln2g, const float* ln2b,
                      const Scratch& S)
{
    const long DD = (long)Dc * Dc;
    const float one = 1.0f;
    const float scl = 1.0f / sqrtf((float)DKc);

    // q(=k) projection
    gemm_tf32<<<dim3(Dc/128, MROWS/128), 128>>>(X, kW + (long)l*DD, kb + (long)l*Dc, S.cat,
                                                MROWS, Dc, Dc, 0, 0, 0, one, 0);
    to_heads<<<(MROWS*Dc/4)/256, 256>>>(S.cat, S.qk);
    // v projection (head-transposed output for NT att@v)
    gemm_tf32<<<dim3(Dc/128, MROWS/128), 128>>>(Vin, vW + (long)l*DD, vb + (long)l*Dc, S.cat,
                                                MROWS, Dc, Dc, 0, 0, 0, one, 0);
    to_heads_t<<<(MROWS*Dc/4)/256, 256>>>(S.cat, S.v);

    // scores = q @ q^T / sqrt(dk), batched over B*H
    gemm_tf32<<<dim3(Sc/128, Sc/128, Bc*Hc), 128>>>(S.qk, S.qk, nullptr, S.scores,
                                                    Sc, Sc, DKc,
                                                    (long)Sc*DKc, (long)Sc*DKc, (long)Sc*Sc,
                                                    scl, 0);

    compute_ext<<<(Hc*Sc + 255)/256, 256>>>(alphas + (long)l*Hc*Sc*2, gE + (long)l*Hc*Sc*2, S.ext);
    attn_softmax<<<dim3(Sc, Hc, Bc), 512>>>(S.scores, S.ext, gammas + (long)l*Hc, bmask, bmask == 0);

    // att = scores @ v^T (v stored [DK][S] per head -> NT), batched
    gemm_tf32<<<dim3(DKc/128, Sc/128, Bc*Hc), 128>>>(S.scores, S.v, nullptr, S.att,
                                                     Sc, DKc, Sc,
                                                     (long)Sc*Sc, (long)DKc*Sc, (long)Sc*DKc,
                                                     one, 0);
    from_heads<<<(MROWS*Dc/4)/256, 256>>>(S.att, S.cat);

    // output projection + residual LN
    gemm_tf32<<<dim3(Dc/128, MROWS/128), 128>>>(S.cat, oW + (long)l*DD, ob + (long)l*Dc, S.proj,
                                                MROWS, Dc, Dc, 0, 0, 0, one, 0);
    add_ln<<<MROWS, 256>>>(X, S.proj, ln1g + (long)l*Dc, ln1b + (long)l*Dc, outbuf);

    if (apply_pos) {
        gemm_tf32<<<dim3(DFFc/128, MROWS/128), 128>>>(outbuf, w1 + (long)l*DFFc*Dc, b1 + (long)l*DFFc, S.ff,
                                                      MROWS, DFFc, Dc, 0, 0, 0, one, 1);
        gemm_tf32<<<dim3(Dc/128, MROWS/128), 128>>>(S.ff, w2 + (long)l*Dc*DFFc, b2 + (long)l*Dc, S.proj,
                                                    MROWS, Dc, DFFc, 0, 0, 0, one, 0);
        add_ln<<<MROWS, 256>>>(outbuf, S.proj, ln2g + (long)l*Dc, ln2b + (long)l*Dc, outbuf);
    }
}

extern "C" void kernel_launch(void* const* d_in, const int* in_sizes, int n_in,
                              void* d_out, int out_size)
{
    const float* q_embed  = (const float*)d_in[0];
    const float* qa_embed = (const float*)d_in[1];
    const float* kW = (const float*)d_in[2];
    const float* kb = (const float*)d_in[3];
    const float* vW = (const float*)d_in[4];
    const float* vb = (const float*)d_in[5];
    const float* oW = (const float*)d_in[6];
    const float* ob = (const float*)d_in[7];
    const float* gammas = (const float*)d_in[8];
    const float* alphas = (const float*)d_in[9];
    const float* ln1g = (const float*)d_in[10];
    const float* ln1b = (const float*)d_in[11];
    const float* w1 = (const float*)d_in[12];
    const float* b1 = (const float*)d_in[13];
    const float* w2 = (const float*)d_in[14];
    const float* b2 = (const float*)d_in[15];
    const float* ln2g = (const float*)d_in[16];
    const float* ln2b = (const float*)d_in[17];
    const float* gE = (const float*)d_in[18];
    float* out = (float*)d_out;

    Scratch S;
    cudaGetSymbolAddress((void**)&S.y, g_y);
    cudaGetSymbolAddress((void**)&S.xb, g_xb);
    cudaGetSymbolAddress((void**)&S.cat, g_cat);
    cudaGetSymbolAddress((void**)&S.proj, g_proj);
    cudaGetSymbolAddress((void**)&S.qk, g_qk);
    cudaGetSymbolAddress((void**)&S.v, g_v);
    cudaGetSymbolAddress((void**)&S.att, g_att);
    cudaGetSymbolAddress((void**)&S.scores, g_scores);
    cudaGetSymbolAddress((void**)&S.ff, g_ff);
    cudaGetSymbolAddress((void**)&S.ext, g_ext);

    run_layer(qa_embed, qa_embed, S.y, 0, 1, 1,
              kW, kb, vW, vb, oW, ob, gammas, alphas, gE,
              ln1g, ln1b, w1, b1, w2, b2, ln2g, ln2b, S);
    run_layer(q_embed, q_embed, S.xb, 1, 1, 0,
              kW, kb, vW, vb, oW, ob, gammas, alphas, gE,
              ln1g, ln1b, w1, b1, w2, b2, ln2g, ln2b, S);
    run_layer(S.xb, S.y, out, 2, 0, 1,
              kW, kb, vW, vb, oW, ob, gammas, alphas, gE,
              ln1g, ln1b, w1, b1, w2, b2, ln2g, ln2b, S);
}